// round 1
// baseline (speedup 1.0000x reference)
#include <cuda_runtime.h>
#include <cstdint>

#define T_STEPS 8192
#define H_DIM 256
#define E_DIM 256
#define G_DIM 1024   // 4*H
#define CL 8         // cluster size (portable max)

// 32 MB scratch for xg = emb@W_ih^T + bias  (allocation-free rule: device global)
__device__ float g_xg[(size_t)T_STEPS * G_DIM];

// ---------------------------------------------------------------------------
// helpers
// ---------------------------------------------------------------------------
__device__ __forceinline__ uint32_t smem_u32(const void* p) {
    uint32_t a;
    asm("{ .reg .u64 t; cvta.to.shared.u64 t, %1; cvt.u32.u64 %0, t; }"
        : "=r"(a) : "l"(p));
    return a;
}

__device__ __forceinline__ void ffma2(unsigned long long& d,
                                      unsigned long long a,
                                      unsigned long long b) {
    asm("fma.rn.f32x2 %0, %1, %2, %0;" : "+l"(d) : "l"(a), "l"(b));
}

__device__ __forceinline__ float lo32(unsigned long long v) {
    return __uint_as_float((uint32_t)v);
}
__device__ __forceinline__ float hi32(unsigned long long v) {
    return __uint_as_float((uint32_t)(v >> 32));
}

__device__ __forceinline__ float fast_sigmoid(float x) {
    return __fdividef(1.0f, 1.0f + __expf(-x));
}
// tanh(x) = 1 - 2/(e^{2x}+1): safe at both saturations (inf -> 1, 0 -> -1)
__device__ __forceinline__ float fast_tanh(float x) {
    return 1.0f - __fdividef(2.0f, __expf(2.0f * x) + 1.0f);
}

__device__ __forceinline__ void mbar_wait_cluster(uint32_t addr, uint32_t parity) {
    uint32_t done;
    asm volatile(
        "{\n\t.reg .pred p;\n\t"
        "mbarrier.try_wait.parity.acquire.cluster.shared::cta.b64 p, [%1], %2;\n\t"
        "selp.b32 %0, 1, 0, p;\n\t}"
        : "=r"(done) : "r"(addr), "r"(parity) : "memory");
    if (!done) {
        asm volatile(
            "{\n\t.reg .pred P1;\n"
            "WL_%=:\n\t"
            "mbarrier.try_wait.parity.acquire.cluster.shared::cta.b64 P1, [%0], %1, 0x989680;\n\t"
            "@P1 bra.uni WD_%=;\n\t"
            "bra.uni WL_%=;\n"
            "WD_%=:\n\t}"
            :: "r"(addr), "r"(parity) : "memory");
    }
}

// ---------------------------------------------------------------------------
// Kernel A: xg[t][r] = sum_k emb[tokens[t]][k] * W_ih[r][k] + (b_ih[r]+b_hh[r])
// 128x128 tile per CTA, BK=32, 256 threads, 8x8 micro-tile.
// ---------------------------------------------------------------------------
__global__ __launch_bounds__(256) void xg_gemm(const int* __restrict__ tokens,
                                               const float* __restrict__ emb,
                                               const float* __restrict__ Wih,
                                               const float* __restrict__ bih,
                                               const float* __restrict__ bhh) {
    __shared__ __align__(16) float As[32][132];
    __shared__ __align__(16) float Bs[32][132];
    __shared__ int stok[128];

    const int tid = threadIdx.x;
    const int t0 = blockIdx.y * 128;
    const int r0 = blockIdx.x * 128;

    if (tid < 128) stok[tid] = tokens[t0 + tid];
    __syncthreads();

    const int ty = tid >> 4;   // 0..15
    const int tx = tid & 15;   // 0..15

    float acc[8][8];
#pragma unroll
    for (int i = 0; i < 8; i++)
#pragma unroll
        for (int j = 0; j < 8; j++) acc[i][j] = 0.0f;

    for (int k0 = 0; k0 < E_DIM; k0 += 32) {
#pragma unroll
        for (int q = 0; q < 4; q++) {
            int v = q * 256 + tid;      // 0..1023
            int row = v >> 3;           // 0..127
            int c4 = v & 7;             // float4 index within 32-wide chunk
            float4 a = *(const float4*)(emb + (size_t)stok[row] * E_DIM + k0 + c4 * 4);
            As[c4 * 4 + 0][row] = a.x; As[c4 * 4 + 1][row] = a.y;
            As[c4 * 4 + 2][row] = a.z; As[c4 * 4 + 3][row] = a.w;
            float4 b = *(const float4*)(Wih + (size_t)(r0 + row) * E_DIM + k0 + c4 * 4);
            Bs[c4 * 4 + 0][row] = b.x; Bs[c4 * 4 + 1][row] = b.y;
            Bs[c4 * 4 + 2][row] = b.z; Bs[c4 * 4 + 3][row] = b.w;
        }
        __syncthreads();

#pragma unroll
        for (int k = 0; k < 32; k++) {
            float a[8], b[8];
            float4 a0 = *(const float4*)&As[k][ty * 8];
            float4 a1 = *(const float4*)&As[k][ty * 8 + 4];
            float4 b0 = *(const float4*)&Bs[k][tx * 8];
            float4 b1 = *(const float4*)&Bs[k][tx * 8 + 4];
            a[0]=a0.x; a[1]=a0.y; a[2]=a0.z; a[3]=a0.w;
            a[4]=a1.x; a[5]=a1.y; a[6]=a1.z; a[7]=a1.w;
            b[0]=b0.x; b[1]=b0.y; b[2]=b0.z; b[3]=b0.w;
            b[4]=b1.x; b[5]=b1.y; b[6]=b1.z; b[7]=b1.w;
#pragma unroll
            for (int i = 0; i < 8; i++)
#pragma unroll
                for (int j = 0; j < 8; j++)
                    acc[i][j] = fmaf(a[i], b[j], acc[i][j]);
        }
        __syncthreads();
    }

#pragma unroll
    for (int j = 0; j < 8; j++) {
        int r = r0 + tx * 8 + j;
        float bias = bih[r] + bhh[r];
#pragma unroll
        for (int i = 0; i < 8; i++) {
            g_xg[(size_t)(t0 + ty * 8 + i) * G_DIM + r] = acc[i][j] + bias;
        }
    }
}

// ---------------------------------------------------------------------------
// Kernel B: persistent 8-CTA cluster LSTM scan.
//   CTA rank owns h elements [rank*32, rank*32+32).
//   Warp w: 4 elements (4w..4w+3). Lane l: pair p=l&7 (2 gate rows), K-slice s=l>>3 (64 wide).
//   Weights in registers (128 floats/thread). h replicated in every CTA's SMEM,
//   double-buffered; producers push new h to all 8 CTAs + release-arrive on all
//   8 mbarriers; everyone acquire-waits (256 arrivals/phase).
// ---------------------------------------------------------------------------
__global__ __launch_bounds__(256, 1) __cluster_dims__(CL, 1, 1)
void lstm_scan(const float* __restrict__ Whh, float* __restrict__ out) {
    __shared__ __align__(16) float hbuf[2][H_DIM];
    __shared__ __align__(8) unsigned long long bar;

    const uint32_t smem_h = smem_u32(&hbuf[0][0]);
    const uint32_t smem_bar = smem_u32(&bar);

    const int tid = threadIdx.x;
    const int w = tid >> 5;
    const int ln = tid & 31;
    const int p = ln & 7;      // row pair within warp
    const int s = ln >> 3;     // K-slice (0..3), 64 elements each
    uint32_t rank;
    asm("mov.u32 %0, %%cluster_ctarank;" : "=r"(rank));

    const int e_loc = 4 * w + (p >> 1);
    const int e_glob = (int)rank * 32 + e_loc;
    const int gate0 = 2 * (p & 1);                 // 0 -> rows (i,f); 2 -> rows (g,o)
    const int r0 = (gate0 + 0) * H_DIM + e_glob;
    const int r1 = (gate0 + 1) * H_DIM + e_glob;
    const int kbase = s * 64;

    // weights into registers: 2 rows x 64 K, packed f32x2
    unsigned long long wA[32], wB[32];
#pragma unroll
    for (int i = 0; i < 32; i++) {
        wA[i] = *(const unsigned long long*)(Whh + (size_t)r0 * H_DIM + kbase + 2 * i);
        wB[i] = *(const unsigned long long*)(Whh + (size_t)r1 * H_DIM + kbase + 2 * i);
    }

    // init h buffers + barrier
    for (int i = tid; i < 2 * H_DIM; i += 256) ((float*)hbuf)[i] = 0.0f;
    if (tid == 0) {
        asm volatile("mbarrier.init.shared.b64 [%0], %1;"
                     :: "r"(smem_bar), "r"(256) : "memory");
    }
    __syncthreads();
    asm volatile("barrier.cluster.arrive.aligned;" ::: "memory");
    asm volatile("barrier.cluster.wait.aligned;" ::: "memory");

    const bool prod = (s == 0) && ((p & 1) == 0);  // lanes 0,2,4,6 of each warp

    uint32_t ph[CL], pb[CL];
    if (prod) {
#pragma unroll
        for (int r = 0; r < CL; r++) {
            asm("mapa.shared::cluster.u32 %0, %1, %2;"
                : "=r"(ph[r]) : "r"(smem_h + (uint32_t)e_glob * 4), "r"(r));
            asm("mapa.shared::cluster.u32 %0, %1, %2;"
                : "=r"(pb[r]) : "r"(smem_bar), "r"(r));
        }
    }

    float c = 0.0f;
    float xn0 = 0.f, xn1 = 0.f, xn2 = 0.f, xn3 = 0.f;
    if (prod) {
        xn0 = g_xg[0 * H_DIM + e_glob];
        xn1 = g_xg[1 * H_DIM + e_glob];
        xn2 = g_xg[2 * H_DIM + e_glob];
        xn3 = g_xg[3 * H_DIM + e_glob];
    }

    for (int t = 0; t < T_STEPS; t++) {
        if (t > 0) mbar_wait_cluster(smem_bar, (uint32_t)((t - 1) & 1));

        float x0 = xn0, x1 = xn1, x2 = xn2, x3 = xn3;
        if (prod) {
            int tn = (t + 1 < T_STEPS) ? (t + 1) : t;   // prefetch next step's xg
            const float* xr = g_xg + (size_t)tn * G_DIM + e_glob;
            xn0 = xr[0];
            xn1 = xr[256];
            xn2 = xr[512];
            xn3 = xr[768];
        }

        // dot products over this lane's 64-wide K slice (packed f32x2 FMA)
        const ulonglong2* h2 =
            (const ulonglong2*)((const char*)hbuf + (t & 1) * H_DIM * 4 + kbase * 4);
        unsigned long long a0 = 0ull, a1 = 0ull, b0 = 0ull, b1 = 0ull;
#pragma unroll
        for (int i = 0; i < 16; i++) {
            ulonglong2 hv = h2[i];
            ffma2(a0, wA[2 * i + 0], hv.x);
            ffma2(a1, wA[2 * i + 1], hv.y);
            ffma2(b0, wB[2 * i + 0], hv.x);
            ffma2(b1, wB[2 * i + 1], hv.y);
        }
        float s0 = (lo32(a0) + hi32(a0)) + (lo32(a1) + hi32(a1));
        float s1 = (lo32(b0) + hi32(b0)) + (lo32(b1) + hi32(b1));

        // reduce across the 4 K-slices (lanes xor 8, xor 16)
        s0 += __shfl_xor_sync(0xFFFFFFFFu, s0, 8);
        s1 += __shfl_xor_sync(0xFFFFFFFFu, s1, 8);
        s0 += __shfl_xor_sync(0xFFFFFFFFu, s0, 16);
        s1 += __shfl_xor_sync(0xFFFFFFFFu, s1, 16);
        // partner lane (xor 1) holds (g,o) sums
        float sg = __shfl_xor_sync(0xFFFFFFFFu, s0, 1);
        float so = __shfl_xor_sync(0xFFFFFFFFu, s1, 1);

        if (prod) {
            float iv = fast_sigmoid(s0 + x0);
            float fv = fast_sigmoid(s1 + x1);
            float gv = fast_tanh(sg + x2);
            float ov = fast_sigmoid(so + x3);
            c = fv * c + iv * gv;
            float hv = ov * fast_tanh(c);

            out[(size_t)t * H_DIM + e_glob] = hv;
            if (t == T_STEPS - 1) {
                out[(size_t)T_STEPS * H_DIM + e_glob] = hv;           // h_last
                out[(size_t)T_STEPS * H_DIM + H_DIM + e_glob] = c;    // c_last
            }

            if (t < T_STEPS - 1) {
                uint32_t boff = (uint32_t)((t + 1) & 1) * H_DIM * 4;
#pragma unroll
                for (int r = 0; r < CL; r++)
                    asm volatile("st.shared::cluster.f32 [%0], %1;"
                                 :: "r"(ph[r] + boff), "f"(hv) : "memory");
#pragma unroll
                for (int r = 0; r < CL; r++)
                    asm volatile(
                        "mbarrier.arrive.release.cluster.shared::cluster.b64 _, [%0];"
                        :: "r"(pb[r]) : "memory");
            }
        }
    }
}

// ---------------------------------------------------------------------------
extern "C" void kernel_launch(void* const* d_in, const int* in_sizes, int n_in,
                              void* d_out, int out_size) {
    const int* tokens = (const int*)d_in[0];
    const float* emb = (const float*)d_in[1];
    const float* Wih = (const float*)d_in[2];
    const float* Whh = (const float*)d_in[3];
    const float* bih = (const float*)d_in[4];
    const float* bhh = (const float*)d_in[5];
    float* out = (float*)d_out;

    dim3 gA(8, 64);                 // 1024/128 gate-row tiles x 8192/128 token tiles
    xg_gemm<<<gA, 256>>>(tokens, emb, Wih, bih, bhh);
    lstm_scan<<<CL, 256>>>(Whh, out);
}

// round 3
// speedup vs baseline: 2.3357x; 2.3357x over previous
#include <cuda_runtime.h>
#include <cstdint>

#define T_STEPS 8192
#define H_DIM 256
#define E_DIM 256
#define G_DIM 1024   // 4*H
#define CL 8         // cluster size (portable max)

// 32 MB scratch for xg = emb@W_ih^T + bias  (allocation-free rule: device global)
__device__ float g_xg[(size_t)T_STEPS * G_DIM];

// ---------------------------------------------------------------------------
// helpers
// ---------------------------------------------------------------------------
__device__ __forceinline__ uint32_t smem_u32(const void* p) {
    uint32_t a;
    asm("{ .reg .u64 t; cvta.to.shared.u64 t, %1; cvt.u32.u64 %0, t; }"
        : "=r"(a) : "l"(p));
    return a;
}

__device__ __forceinline__ void ffma2(unsigned long long& d,
                                      unsigned long long a,
                                      unsigned long long b) {
    asm("fma.rn.f32x2 %0, %1, %2, %0;" : "+l"(d) : "l"(a), "l"(b));
}
__device__ __forceinline__ void fadd2(unsigned long long& d,
                                      unsigned long long a) {
    asm("add.rn.f32x2 %0, %0, %1;" : "+l"(d) : "l"(a));
}

__device__ __forceinline__ float lo32(unsigned long long v) {
    return __uint_as_float((uint32_t)v);
}
__device__ __forceinline__ float hi32(unsigned long long v) {
    return __uint_as_float((uint32_t)(v >> 32));
}

__device__ __forceinline__ float fast_sigmoid(float x) {
    return __fdividef(1.0f, 1.0f + __expf(-x));
}
// tanh(x) = 1 - 2/(e^{2x}+1): safe at both saturations
__device__ __forceinline__ float fast_tanh(float x) {
    return 1.0f - __fdividef(2.0f, __expf(2.0f * x) + 1.0f);
}

__device__ __forceinline__ void mbar_wait_cluster(uint32_t addr, uint32_t parity) {
    uint32_t done;
    asm volatile(
        "{\n\t.reg .pred p;\n\t"
        "mbarrier.try_wait.parity.acquire.cluster.shared::cta.b64 p, [%1], %2;\n\t"
        "selp.b32 %0, 1, 0, p;\n\t}"
        : "=r"(done) : "r"(addr), "r"(parity) : "memory");
    if (!done) {
        asm volatile(
            "{\n\t.reg .pred P1;\n"
            "WL_%=:\n\t"
            "mbarrier.try_wait.parity.acquire.cluster.shared::cta.b64 P1, [%0], %1, 0x989680;\n\t"
            "@P1 bra.uni WD_%=;\n\t"
            "bra.uni WL_%=;\n"
            "WD_%=:\n\t}"
            :: "r"(addr), "r"(parity) : "memory");
    }
}

// ---------------------------------------------------------------------------
// Kernel A: xg[t][r] = sum_k emb[tokens[t]][k] * W_ih[r][k] + (b_ih[r]+b_hh[r])
// ---------------------------------------------------------------------------
__global__ __launch_bounds__(256) void xg_gemm(const int* __restrict__ tokens,
                                               const float* __restrict__ emb,
                                               const float* __restrict__ Wih,
                                               const float* __restrict__ bih,
                                               const float* __restrict__ bhh) {
    __shared__ __align__(16) float As[32][132];
    __shared__ __align__(16) float Bs[32][132];
    __shared__ int stok[128];

    const int tid = threadIdx.x;
    const int t0 = blockIdx.y * 128;
    const int r0 = blockIdx.x * 128;

    if (tid < 128) stok[tid] = tokens[t0 + tid];
    __syncthreads();

    const int ty = tid >> 4;
    const int tx = tid & 15;

    float acc[8][8];
#pragma unroll
    for (int i = 0; i < 8; i++)
#pragma unroll
        for (int j = 0; j < 8; j++) acc[i][j] = 0.0f;

    for (int k0 = 0; k0 < E_DIM; k0 += 32) {
#pragma unroll
        for (int q = 0; q < 4; q++) {
            int v = q * 256 + tid;
            int row = v >> 3;
            int c4 = v & 7;
            float4 a = *(const float4*)(emb + (size_t)stok[row] * E_DIM + k0 + c4 * 4);
            As[c4 * 4 + 0][row] = a.x; As[c4 * 4 + 1][row] = a.y;
            As[c4 * 4 + 2][row] = a.z; As[c4 * 4 + 3][row] = a.w;
            float4 b = *(const float4*)(Wih + (size_t)(r0 + row) * E_DIM + k0 + c4 * 4);
            Bs[c4 * 4 + 0][row] = b.x; Bs[c4 * 4 + 1][row] = b.y;
            Bs[c4 * 4 + 2][row] = b.z; Bs[c4 * 4 + 3][row] = b.w;
        }
        __syncthreads();

#pragma unroll
        for (int k = 0; k < 32; k++) {
            float a[8], b[8];
            float4 a0 = *(const float4*)&As[k][ty * 8];
            float4 a1 = *(const float4*)&As[k][ty * 8 + 4];
            float4 b0 = *(const float4*)&Bs[k][tx * 8];
            float4 b1 = *(const float4*)&Bs[k][tx * 8 + 4];
            a[0]=a0.x; a[1]=a0.y; a[2]=a0.z; a[3]=a0.w;
            a[4]=a1.x; a[5]=a1.y; a[6]=a1.z; a[7]=a1.w;
            b[0]=b0.x; b[1]=b0.y; b[2]=b0.z; b[3]=b0.w;
            b[4]=b1.x; b[5]=b1.y; b[6]=b1.z; b[7]=b1.w;
#pragma unroll
            for (int i = 0; i < 8; i++)
#pragma unroll
                for (int j = 0; j < 8; j++)
                    acc[i][j] = fmaf(a[i], b[j], acc[i][j]);
        }
        __syncthreads();
    }

#pragma unroll
    for (int j = 0; j < 8; j++) {
        int r = r0 + tx * 8 + j;
        float bias = bih[r] + bhh[r];
#pragma unroll
        for (int i = 0; i < 8; i++) {
            g_xg[(size_t)(t0 + ty * 8 + i) * G_DIM + r] = acc[i][j] + bias;
        }
    }
}

// ---------------------------------------------------------------------------
// Kernel B: persistent 8-CTA cluster LSTM scan, message-minimal exchange.
//   CTA rank owns h elements [rank*32, rank*32+32) -> its 128 gate rows.
//   Phase 1 (all 8 warps): warp w covers K-slice [32w,32w+32); lane e computes
//     4 gate partials for element e; STS partials.
//   Phase 2 (warp 0): lane e sums 8 partials/gate, applies activations fully
//     in-lane, updates c, writes hv to staging + out.
//   Phase 3 (all warps): warp w pushes the CTA's 32 h-values to dest CTA w
//     as 8 x st.shared::cluster.v4 (lanes 0-7), then ONE elected
//     release-arrive per (srcCTA,dest). Barrier expects 8 arrives/phase.
// ---------------------------------------------------------------------------
__global__ __launch_bounds__(256, 1) __cluster_dims__(CL, 1, 1)
void lstm_scan(const float* __restrict__ Whh, float* __restrict__ out) {
    __shared__ __align__(16) float hbuf[2][H_DIM];
    __shared__ __align__(16) float part[8][32][4];   // [warp][elem][gate]
    __shared__ __align__(16) float hstage[32];
    __shared__ __align__(8) unsigned long long bar;

    const uint32_t smem_h = smem_u32(&hbuf[0][0]);
    const uint32_t smem_bar = smem_u32(&bar);

    const int tid = threadIdx.x;
    const int w = tid >> 5;    // warp = K-slice and push-destination
    const int e = tid & 31;    // element within CTA's 32
    uint32_t rank;
    asm("mov.u32 %0, %%cluster_ctarank;" : "=r"(rank));

    const int E = (int)rank * 32 + e;   // global h element

    // weights: 4 gate rows x 32 K (this warp's slice), packed f32x2.
    // wt[g][j] covers K floats [32w + 2j, 32w + 2j + 2).
    unsigned long long wt[4][16];
#pragma unroll
    for (int g = 0; g < 4; g++) {
        const unsigned long long* wr =
            (const unsigned long long*)(Whh + (size_t)(g * H_DIM + E) * H_DIM + 32 * w);
#pragma unroll
        for (int i = 0; i < 16; i++) wt[g][i] = wr[i];
    }

    // init h buffers + barrier
    for (int i = tid; i < 2 * H_DIM; i += 256) ((float*)hbuf)[i] = 0.0f;
    if (tid == 0) {
        asm volatile("mbarrier.init.shared.b64 [%0], %1;"
                     :: "r"(smem_bar), "r"(CL) : "memory");
    }
    __syncthreads();
    asm volatile("barrier.cluster.arrive.aligned;" ::: "memory");
    asm volatile("barrier.cluster.wait.aligned;" ::: "memory");

    // remote addresses for this warp's destination CTA (= w)
    uint32_t ph, pb;
    asm("mapa.shared::cluster.u32 %0, %1, %2;" : "=r"(ph) : "r"(smem_h), "r"(w));
    asm("mapa.shared::cluster.u32 %0, %1, %2;" : "=r"(pb) : "r"(smem_bar), "r"(w));

    float c = 0.0f;
    float xn0 = 0.f, xn1 = 0.f, xn2 = 0.f, xn3 = 0.f;
    if (w == 0) {
        xn0 = g_xg[0 * H_DIM + E];
        xn1 = g_xg[1 * H_DIM + E];
        xn2 = g_xg[2 * H_DIM + E];
        xn3 = g_xg[3 * H_DIM + E];
    }

    for (int t = 0; t < T_STEPS; t++) {
        if (t > 0) mbar_wait_cluster(smem_bar, (uint32_t)((t - 1) & 1));

        // ---- phase 1: load h slice [32w,32w+32), 128 MACs/lane ----
        // hh[j] covers K floats [32w + 2j, 32w + 2j + 2) -> pairs with wt[g][j].
        const ulonglong2* hp =
            (const ulonglong2*)((const char*)hbuf + (t & 1) * H_DIM * 4 + w * 128);
        unsigned long long hh[16];
#pragma unroll
        for (int i = 0; i < 8; i++) {
            ulonglong2 q = hp[i];
            hh[2 * i + 0] = q.x;
            hh[2 * i + 1] = q.y;
        }

        unsigned long long a0 = 0ull, a1 = 0ull, a2 = 0ull, a3 = 0ull;
#pragma unroll
        for (int j = 0; j < 16; j++) {
            ffma2(a0, wt[0][j], hh[j]);
            ffma2(a1, wt[1][j], hh[j]);
            ffma2(a2, wt[2][j], hh[j]);
            ffma2(a3, wt[3][j], hh[j]);
        }

        float4 p;
        p.x = lo32(a0) + hi32(a0);
        p.y = lo32(a1) + hi32(a1);
        p.z = lo32(a2) + hi32(a2);
        p.w = lo32(a3) + hi32(a3);
        *(float4*)&part[w][e][0] = p;
        __syncthreads();

        // ---- phase 2: warp 0 finishes reduction + activations ----
        if (w == 0) {
            unsigned long long sA = 0ull, sB = 0ull;
#pragma unroll
            for (int ww = 0; ww < 8; ww++) {
                ulonglong2 v = *(const ulonglong2*)&part[ww][e][0];
                fadd2(sA, v.x);
                fadd2(sB, v.y);
            }
            float x0 = xn0, x1 = xn1, x2 = xn2, x3 = xn3;
            {
                int tn = (t + 1 < T_STEPS) ? (t + 1) : t;
                const float* xr = g_xg + (size_t)tn * G_DIM + E;
                xn0 = xr[0]; xn1 = xr[256]; xn2 = xr[512]; xn3 = xr[768];
            }
            float iv = fast_sigmoid(lo32(sA) + x0);
            float fv = fast_sigmoid(hi32(sA) + x1);
            float gv = fast_tanh(lo32(sB) + x2);
            float ov = fast_sigmoid(hi32(sB) + x3);
            c = fv * c + iv * gv;
            float hv = ov * fast_tanh(c);

            hstage[e] = hv;
            out[(size_t)t * H_DIM + E] = hv;
            if (t == T_STEPS - 1) {
                out[(size_t)T_STEPS * H_DIM + E] = hv;
                out[(size_t)T_STEPS * H_DIM + H_DIM + E] = c;
            }
        }
        __syncthreads();

        // ---- phase 3: warp w pushes all 32 values to dest CTA w ----
        if (t < T_STEPS - 1) {
            if (e < 8) {
                float4 hv4 = *(const float4*)&hstage[e * 4];
                uint32_t dst = ph + (uint32_t)((t + 1) & 1) * (H_DIM * 4)
                             + rank * 128 + (uint32_t)e * 16;
                asm volatile("st.shared::cluster.v4.f32 [%0], {%1,%2,%3,%4};"
                             :: "r"(dst), "f"(hv4.x), "f"(hv4.y),
                                "f"(hv4.z), "f"(hv4.w) : "memory");
            }
            __syncwarp();
            if (e == 0) {
                asm volatile(
                    "mbarrier.arrive.release.cluster.shared::cluster.b64 _, [%0];"
                    :: "r"(pb) : "memory");
            }
        }
    }
}

// ---------------------------------------------------------------------------
extern "C" void kernel_launch(void* const* d_in, const int* in_sizes, int n_in,
                              void* d_out, int out_size) {
    const int* tokens = (const int*)d_in[0];
    const float* emb = (const float*)d_in[1];
    const float* Wih = (const float*)d_in[2];
    const float* Whh = (const float*)d_in[3];
    const float* bih = (const float*)d_in[4];
    const float* bhh = (const float*)d_in[5];
    float* out = (float*)d_out;

    dim3 gA(8, 64);
    xg_gemm<<<gA, 256>>>(tokens, emb, Wih, bih, bhh);
    lstm_scan<<<CL, 256>>>(Whh, out);
}

// round 4
// speedup vs baseline: 2.7356x; 1.1712x over previous
#include <cuda_runtime.h>
#include <cstdint>

#define T_STEPS 8192
#define H_DIM 256
#define E_DIM 256
#define G_DIM 1024   // 4*H
#define CL 8         // cluster size (portable max)

// 32 MB scratch for xg = emb@W_ih^T + bias  (allocation-free rule: device global)
__device__ float g_xg[(size_t)T_STEPS * G_DIM];

// ---------------------------------------------------------------------------
// helpers
// ---------------------------------------------------------------------------
__device__ __forceinline__ uint32_t smem_u32(const void* p) {
    uint32_t a;
    asm("{ .reg .u64 t; cvta.to.shared.u64 t, %1; cvt.u32.u64 %0, t; }"
        : "=r"(a) : "l"(p));
    return a;
}

__device__ __forceinline__ void ffma2(unsigned long long& d,
                                      unsigned long long a,
                                      unsigned long long b) {
    asm("fma.rn.f32x2 %0, %1, %2, %0;" : "+l"(d) : "l"(a), "l"(b));
}

__device__ __forceinline__ float lo32(unsigned long long v) {
    return __uint_as_float((uint32_t)v);
}
__device__ __forceinline__ float hi32(unsigned long long v) {
    return __uint_as_float((uint32_t)(v >> 32));
}

__device__ __forceinline__ float fast_sigmoid(float x) {
    return __fdividef(1.0f, 1.0f + __expf(-x));
}
// tanh(x) = 1 - 2/(e^{2x}+1): safe at both saturations
__device__ __forceinline__ float fast_tanh(float x) {
    return 1.0f - __fdividef(2.0f, __expf(2.0f * x) + 1.0f);
}

__device__ __forceinline__ void mbar_wait(uint32_t addr, uint32_t parity) {
    uint32_t done;
    asm volatile(
        "{\n\t.reg .pred p;\n\t"
        "mbarrier.try_wait.parity.acquire.cta.shared::cta.b64 p, [%1], %2;\n\t"
        "selp.b32 %0, 1, 0, p;\n\t}"
        : "=r"(done) : "r"(addr), "r"(parity) : "memory");
    if (!done) {
        asm volatile(
            "{\n\t.reg .pred P1;\n"
            "WL_%=:\n\t"
            "mbarrier.try_wait.parity.acquire.cta.shared::cta.b64 P1, [%0], %1, 0x989680;\n\t"
            "@P1 bra.uni WD_%=;\n\t"
            "bra.uni WL_%=;\n"
            "WD_%=:\n\t}"
            :: "r"(addr), "r"(parity) : "memory");
    }
}

// ---------------------------------------------------------------------------
// Kernel A: xg[t][r] = sum_k emb[tokens[t]][k] * W_ih[r][k] + (b_ih[r]+b_hh[r])
// ---------------------------------------------------------------------------
__global__ __launch_bounds__(256) void xg_gemm(const int* __restrict__ tokens,
                                               const float* __restrict__ emb,
                                               const float* __restrict__ Wih,
                                               const float* __restrict__ bih,
                                               const float* __restrict__ bhh) {
    __shared__ __align__(16) float As[32][132];
    __shared__ __align__(16) float Bs[32][132];
    __shared__ int stok[128];

    const int tid = threadIdx.x;
    const int t0 = blockIdx.y * 128;
    const int r0 = blockIdx.x * 128;

    if (tid < 128) stok[tid] = tokens[t0 + tid];
    __syncthreads();

    const int ty = tid >> 4;
    const int tx = tid & 15;

    float acc[8][8];
#pragma unroll
    for (int i = 0; i < 8; i++)
#pragma unroll
        for (int j = 0; j < 8; j++) acc[i][j] = 0.0f;

    for (int k0 = 0; k0 < E_DIM; k0 += 32) {
#pragma unroll
        for (int q = 0; q < 4; q++) {
            int v = q * 256 + tid;
            int row = v >> 3;
            int c4 = v & 7;
            float4 a = *(const float4*)(emb + (size_t)stok[row] * E_DIM + k0 + c4 * 4);
            As[c4 * 4 + 0][row] = a.x; As[c4 * 4 + 1][row] = a.y;
            As[c4 * 4 + 2][row] = a.z; As[c4 * 4 + 3][row] = a.w;
            float4 b = *(const float4*)(Wih + (size_t)(r0 + row) * E_DIM + k0 + c4 * 4);
            Bs[c4 * 4 + 0][row] = b.x; Bs[c4 * 4 + 1][row] = b.y;
            Bs[c4 * 4 + 2][row] = b.z; Bs[c4 * 4 + 3][row] = b.w;
        }
        __syncthreads();

#pragma unroll
        for (int k = 0; k < 32; k++) {
            float a[8], b[8];
            float4 a0 = *(const float4*)&As[k][ty * 8];
            float4 a1 = *(const float4*)&As[k][ty * 8 + 4];
            float4 b0 = *(const float4*)&Bs[k][tx * 8];
            float4 b1 = *(const float4*)&Bs[k][tx * 8 + 4];
            a[0]=a0.x; a[1]=a0.y; a[2]=a0.z; a[3]=a0.w;
            a[4]=a1.x; a[5]=a1.y; a[6]=a1.z; a[7]=a1.w;
            b[0]=b0.x; b[1]=b0.y; b[2]=b0.z; b[3]=b0.w;
            b[4]=b1.x; b[5]=b1.y; b[6]=b1.z; b[7]=b1.w;
#pragma unroll
            for (int i = 0; i < 8; i++)
#pragma unroll
                for (int j = 0; j < 8; j++)
                    acc[i][j] = fmaf(a[i], b[j], acc[i][j]);
        }
        __syncthreads();
    }

#pragma unroll
    for (int j = 0; j < 8; j++) {
        int r = r0 + tx * 8 + j;
        float bias = bih[r] + bhh[r];
#pragma unroll
        for (int i = 0; i < 8; i++) {
            g_xg[(size_t)(t0 + ty * 8 + i) * G_DIM + r] = acc[i][j] + bias;
        }
    }
}

// ---------------------------------------------------------------------------
// Kernel B: persistent 8-CTA cluster LSTM scan.
//   h broadcast via cp.async.bulk SMEM->remote SMEM with mbarrier complete_tx
//   (tx-count barriers, no arrive round-trips). Activations distributed
//   across all 8 warps; one __syncthreads per step.
//
//   Warp w owns local elems 4w..4w+3 (global E = 32*rank + 4w + eidx).
//   Lane l: eidx = l&3, K-slice s = l>>2 (8 slices x 32 floats).
//   Each lane: 4 gate-row partial dots over its slice (64 f32x2 FMA),
//   shuffle-reduce over s (xor 4,8,16), lanes 0-3 apply activations (c kept
//   in-lane), STS hv -> hstage[t&1], bar, warp 0 lanes 0-7 bulk-copy 128B to
//   the 8 dest CTAs' hbuf[(t+1)&1] with complete_tx on dest bar[(t+1)&1].
//
//   Barrier protocol (per CTA, two barriers by parity, init count=1):
//     pre-loop: arm b1 (expect_tx 1024B) for t=1.
//     step t:   wait b[t&1] (t>0), parity ((t-1)>>1)&1;
//               tid0 re-arms b[t&1] with expect_tx 1024B for step t+2.
//   Arm-before-send safety: producer sends for t+2 only after its wait(t+1),
//   which needs our t+1 bulk, issued after our arm at step t.
// ---------------------------------------------------------------------------
__global__ __launch_bounds__(256, 1) __cluster_dims__(CL, 1, 1)
void lstm_scan(const float* __restrict__ Whh, float* __restrict__ out) {
    __shared__ __align__(16) float hbuf[2][H_DIM];
    __shared__ __align__(16) float hstage[2][32];
    __shared__ __align__(8) unsigned long long bar2[2];

    const uint32_t smem_h = smem_u32(&hbuf[0][0]);
    const uint32_t smem_stage0 = smem_u32(&hstage[0][0]);
    const uint32_t smem_b0 = smem_u32(&bar2[0]);
    const uint32_t smem_b1 = smem_u32(&bar2[1]);

    const int tid = threadIdx.x;
    const int w = tid >> 5;
    const int l = tid & 31;
    const int eidx = l & 3;
    const int s = l >> 2;
    uint32_t rank;
    asm("mov.u32 %0, %%cluster_ctarank;" : "=r"(rank));

    const int E = (int)rank * 32 + 4 * w + eidx;   // global h element

    // weights: 4 gate rows of element E, K slice [32s, 32s+32), packed f32x2.
    unsigned long long wt[4][16];
#pragma unroll
    for (int g = 0; g < 4; g++) {
        const unsigned long long* wr =
            (const unsigned long long*)(Whh + (size_t)(g * H_DIM + E) * H_DIM + 32 * s);
#pragma unroll
        for (int i = 0; i < 16; i++) wt[g][i] = wr[i];
    }

    // init
    for (int i = tid; i < 2 * H_DIM; i += 256) ((float*)hbuf)[i] = 0.0f;
    if (tid == 0) {
        asm volatile("mbarrier.init.shared.b64 [%0], %1;"
                     :: "r"(smem_b0), "r"(1) : "memory");
        asm volatile("mbarrier.init.shared.b64 [%0], %1;"
                     :: "r"(smem_b1), "r"(1) : "memory");
        // pre-arm b1 for step t=1 (h(1) arrives during step 0)
        asm volatile("mbarrier.arrive.expect_tx.shared.b64 _, [%0], %1;"
                     :: "r"(smem_b1), "r"(H_DIM * 4) : "memory");
    }
    __syncthreads();
    asm volatile("barrier.cluster.arrive.aligned;" ::: "memory");
    asm volatile("barrier.cluster.wait.aligned;" ::: "memory");

    // warp 0, lanes 0-7: remote addresses for dest CTA = lane index
    uint32_t dst_h = 0, dst_b0 = 0, dst_b1 = 0;
    if (w == 0 && l < CL) {
        asm("mapa.shared::cluster.u32 %0, %1, %2;" : "=r"(dst_h) : "r"(smem_h), "r"(l));
        asm("mapa.shared::cluster.u32 %0, %1, %2;" : "=r"(dst_b0) : "r"(smem_b0), "r"(l));
        asm("mapa.shared::cluster.u32 %0, %1, %2;" : "=r"(dst_b1) : "r"(smem_b1), "r"(l));
    }

    float c = 0.0f;
    float xn0 = 0.f, xn1 = 0.f, xn2 = 0.f, xn3 = 0.f;
    if (l < 4) {
        xn0 = g_xg[0 * H_DIM + E];
        xn1 = g_xg[1 * H_DIM + E];
        xn2 = g_xg[2 * H_DIM + E];
        xn3 = g_xg[3 * H_DIM + E];
    }

    for (int t = 0; t < T_STEPS; t++) {
        const uint32_t mybar = (t & 1) ? smem_b1 : smem_b0;
        if (t > 0) mbar_wait(mybar, (uint32_t)(((t - 1) >> 1) & 1));
        if (tid == 0) {
            // re-arm this barrier for its use at step t+2
            asm volatile("mbarrier.arrive.expect_tx.shared.b64 _, [%0], %1;"
                         :: "r"(mybar), "r"(H_DIM * 4) : "memory");
        }

        // ---- partial dots over K slice [32s, 32s+32) ----
        const ulonglong2* hp =
            (const ulonglong2*)((const char*)hbuf + (t & 1) * (H_DIM * 4) + s * 128);
        unsigned long long hh[16];
#pragma unroll
        for (int i = 0; i < 8; i++) {
            ulonglong2 q = hp[i];
            hh[2 * i + 0] = q.x;
            hh[2 * i + 1] = q.y;
        }
        unsigned long long a0 = 0ull, a1 = 0ull, a2 = 0ull, a3 = 0ull;
#pragma unroll
        for (int j = 0; j < 16; j++) {
            ffma2(a0, wt[0][j], hh[j]);
            ffma2(a1, wt[1][j], hh[j]);
            ffma2(a2, wt[2][j], hh[j]);
            ffma2(a3, wt[3][j], hh[j]);
        }
        float si = lo32(a0) + hi32(a0);
        float sf = lo32(a1) + hi32(a1);
        float sg = lo32(a2) + hi32(a2);
        float so = lo32(a3) + hi32(a3);

        // reduce across 8 K-slices (lane bits 2,3,4)
#pragma unroll
        for (int off = 4; off <= 16; off <<= 1) {
            si += __shfl_xor_sync(0xFFFFFFFFu, si, off);
            sf += __shfl_xor_sync(0xFFFFFFFFu, sf, off);
            sg += __shfl_xor_sync(0xFFFFFFFFu, sg, off);
            so += __shfl_xor_sync(0xFFFFFFFFu, so, off);
        }

        // ---- activations in lanes 0-3 of every warp ----
        if (l < 4) {
            float x0 = xn0, x1 = xn1, x2 = xn2, x3 = xn3;
            {
                int tn = (t + 1 < T_STEPS) ? (t + 1) : t;
                const float* xr = g_xg + (size_t)tn * G_DIM + E;
                xn0 = xr[0]; xn1 = xr[256]; xn2 = xr[512]; xn3 = xr[768];
            }
            float iv = fast_sigmoid(si + x0);
            float fv = fast_sigmoid(sf + x1);
            float gv = fast_tanh(sg + x2);
            float ov = fast_sigmoid(so + x3);
            c = fv * c + iv * gv;
            float hv = ov * fast_tanh(c);

            hstage[t & 1][4 * w + eidx] = hv;
            out[(size_t)t * H_DIM + E] = hv;
            if (t == T_STEPS - 1) {
                out[(size_t)T_STEPS * H_DIM + E] = hv;
                out[(size_t)T_STEPS * H_DIM + H_DIM + E] = c;
            }
        }
        __syncthreads();

        // ---- broadcast: warp 0 lanes 0-7 bulk-copy 128B to each dest CTA ----
        if (t < T_STEPS - 1) {
            if (w == 0 && l < CL) {
                asm volatile("fence.proxy.async.shared::cta;" ::: "memory");
                uint32_t src = smem_stage0 + (uint32_t)(t & 1) * 128;
                uint32_t dst = dst_h + (uint32_t)((t + 1) & 1) * (H_DIM * 4)
                             + rank * 128;
                uint32_t dbar = ((t + 1) & 1) ? dst_b1 : dst_b0;
                asm volatile(
                    "cp.async.bulk.shared::cluster.shared::cta.mbarrier::complete_tx::bytes "
                    "[%0], [%1], %2, [%3];"
                    :: "r"(dst), "r"(src), "r"(128), "r"(dbar) : "memory");
            }
        }
    }
}

// ---------------------------------------------------------------------------
extern "C" void kernel_launch(void* const* d_in, const int* in_sizes, int n_in,
                              void* d_out, int out_size) {
    const int* tokens = (const int*)d_in[0];
    const float* emb = (const float*)d_in[1];
    const float* Wih = (const float*)d_in[2];
    const float* Whh = (const float*)d_in[3];
    const float* bih = (const float*)d_in[4];
    const float* bhh = (const float*)d_in[5];
    float* out = (float*)d_out;

    dim3 gA(8, 64);
    xg_gemm<<<gA, 256>>>(tokens, emb, Wih, bih, bhh);
    lstm_scan<<<CL, 256>>>(Whh, out);
}